// round 15
// baseline (speedup 1.0000x reference)
#include <cuda_runtime.h>

#define CUT2 25.0f
#define QS 4            // j-quarter split: 4 warps share one row-block
#define HCAP 128        // per-warp staged-hit capacity (max row degree ~60)
#define NROWS_CAP 65536
#define NGRP_CAP  (NROWS_CAP / 4)
#define MAXCH 32        // max 32-wide j-chunks per row (nat <= 1024)
#define NPK_CAP 131072
#define NSYS_CAP 2048
#define NSYS_SM 257

// Scratch (static __device__, allocation-free).
__device__ float4 g_pk[NPK_CAP];            // (2x,2y,2z,sq) per atom, padded
__device__ uint4  g_mask[(size_t)NGRP_CAP * MAXCH];   // R9-proven layout, 8 MB
__device__ int    g_cntp[(size_t)NROWS_CAP * QS];     // per-(row, quarter)
__device__ int    g_offsets[NROWS_CAP];     // within-system exclusive prefix
__device__ int    g_systot[NSYS_CAP];       // per-system totals

// ---- bit-exact reference arithmetic (DO NOT CHANGE) ----
__device__ __forceinline__ float sqnorm3(float x, float y, float z) {
    return __fadd_rn(__fadd_rn(__fmul_rn(x, x), __fmul_rn(y, y)), __fmul_rn(z, z));
}
// --------------------------------------------------------

// K0: pack (2x, 2y, 2z, sq) per atom; sentinel (0,0,0,1e30) pads each system
// to stride = nch*32 so sweep/output need no bounds checks.
__global__ void prep_kernel(const float* __restrict__ coords, int nat,
                            int stride, int nsys) {
    int idx = blockIdx.x * blockDim.x + threadIdx.x;
    if (idx >= nsys * stride) return;
    int s = idx / stride, j = idx - s * stride;
    float4 r = make_float4(0.f, 0.f, 0.f, 1e30f);
    if (j < nat) {
        const float* p = coords + ((size_t)s * nat + j) * 3;
        float x = p[0], y = p[1], z = p[2];
        r = make_float4(2.0f * x, 2.0f * y, 2.0f * z, sqnorm3(x, y, z));
    }
    g_pk[idx] = r;
}

extern __shared__ float4 s_at[];  // stride entries: (2x, 2y, 2z, sq)

// K1 (R13-proven): row-per-lane mask sweep with j-quarter split. Work item
// (blk, q): lane l owns row 32*blk + l; the warp walks chunks
// c = blk+q, blk+q+QS, ... s_at[j] loads are warp-broadcast. Each lane
// accumulates its row's 32-bit mask in a register (FSETP + predicated OR).
// The negated/halved row regs make the FMA chain produce -2*dot exactly, so
// d = rn(rn(wi+wj) - 2*dot): bit-identical to the reference d12.
__global__ void sweep_kernel(int nat, int nch, int ngroups) {
    int s = blockIdx.x;
    int stride = nch << 5;
    {
        const float4* src = g_pk + (size_t)s * stride;
        for (int t = threadIdx.x; t < stride; t += blockDim.x)
            s_at[t] = src[t];              // LDG.128 -> STS.128 copy
        __syncthreads();
    }

    int lane = threadIdx.x & 31;
    int wj   = (threadIdx.x >> 5) + blockIdx.y * (blockDim.x >> 5);
    int W    = (blockDim.x >> 5) * gridDim.y;
    int NI   = nch * QS;                 // flattened items (blk, q)

    // Zigzag item assignment for balance.
    for (int base_it = 0; base_it * W < NI; base_it++) {
        int it = (base_it & 1) ? ((base_it + 1) * W - 1 - wj)
                               : (base_it * W + wj);
        if (it >= NI) continue;
        int blk = it >> 2, q = it & 3;

        int R = blk << 5;
        int i = R + lane;                  // this lane's row (may be sentinel)
        float4 v = s_at[i];
        float nx = -0.5f * v.x, ny = -0.5f * v.y, nz = -0.5f * v.z;  // exact
        float wi = v.w;

        int g4 = i >> 2;
        bool g4ok = (g4 < ngroups);
        unsigned* mp = ((unsigned*)g_mask) +
                       (((size_t)s * ngroups + g4) * nch) * 4 + (i & 3);
        int cnt = 0;
        int c = blk + q;

        // Diagonal chunk (only item q == 0): keep bits j_local > lane.
        if (q == 0 && c < nch) {
            const float4* jp = s_at + (c << 5);
            unsigned m = 0;
#pragma unroll
            for (int k = 0; k < 32; k++) {
                float4 aj = jp[k];
                float t = __fmul_rn(nx, aj.x);
                t = __fmaf_rn(ny, aj.y, t);
                t = __fmaf_rn(nz, aj.z, t);
                float w = __fadd_rn(wi, aj.w);
                float d = __fadd_rn(w, t);
                if (d < CUT2) m |= (1u << k);
            }
            m &= (0xFFFFFFFEu << lane);
            if (g4ok) mp[(size_t)c << 2] = m;
            cnt += __popc(m);
            c += QS;
        }

        // Clean chunks: all bits valid; sentinels kill j >= nat.
        for (; c < nch; c += QS) {
            const float4* jp = s_at + (c << 5);
            unsigned m = 0;
#pragma unroll
            for (int k = 0; k < 32; k++) {
                float4 aj = jp[k];
                float t = __fmul_rn(nx, aj.x);
                t = __fmaf_rn(ny, aj.y, t);
                t = __fmaf_rn(nz, aj.z, t);
                float w = __fadd_rn(wi, aj.w);
                float d = __fadd_rn(w, t);
                if (d < CUT2) m |= (1u << k);
            }
            if (g4ok) mp[(size_t)c << 2] = m;
            cnt += __popc(m);
        }

        if (i < nat) g_cntp[((size_t)s * nat + i) * QS + q] = cnt;
    }
}

// K2 (R13-proven): per-system exclusive scan; row count = sum of 4 partials.
__global__ void scan_sys_kernel(int nat) {
    __shared__ int wsum[32];
    int s = blockIdx.x;
    int tid = threadIdx.x;
    int lane = tid & 31, w = tid >> 5;

    int v = 0;
    if (tid < nat) {
        int4 p = *(const int4*)&g_cntp[((size_t)s * nat + tid) * QS];
        v = p.x + p.y + p.z + p.w;
    }

    int x = v;
#pragma unroll
    for (int o = 1; o < 32; o <<= 1) {
        int u = __shfl_up_sync(0xffffffffu, x, o);
        if (lane >= o) x += u;
    }
    if (lane == 31) wsum[w] = x;
    __syncthreads();
    if (w == 0) {
        int y = wsum[lane];
#pragma unroll
        for (int o = 1; o < 32; o <<= 1) {
            int u = __shfl_up_sync(0xffffffffu, y, o);
            if (lane >= o) y += u;
        }
        wsum[lane] = y;
    }
    __syncthreads();
    int incl = x + ((w > 0) ? wsum[w - 1] : 0);
    if (tid < nat) g_offsets[s * nat + tid] = incl - v;
    if (tid == nat - 1) g_systot[s] = incl;
}

// K3: fused output. One warp per row; per-warp smem staging of hit
// j-indices (R13-proven), then lane k handles the k-th hit with a SINGLE
// LDG.128 from g_pk (sq precomputed) instead of 3 scattered coord loads.
// d12 via the negated-row form: bit-identical to the reference.
// Output float32 layout (maxp = MAX_PAIRS):
//   [0,M): src   [M,2M): dst    (edge_src = concat(src,dst))
//   [2M,3M): dst [3M,4M): src   (edge_dst = concat(dst,src))
//   [4M,5M): d12 [5M,6M): d12   [6M]: npairs
__global__ void output_kernel(float* __restrict__ out, int maxp, int nrows,
                              int nat, int nsys, int nch, int ngroups,
                              int stride, int WB, float padval, int vec_ok) {
    __shared__ int s_sysoff[NSYS_SM];
    __shared__ int s_hits[8][HCAP];
    int tid = threadIdx.x;
    if (tid < 32) {
        int per = (nsys + 31) >> 5;
        int bbase = tid * per;
        int loc[8];
        int sum = 0;
        for (int u = 0; u < per && u < 8; u++) {
            int idx = bbase + u;
            int t = (idx < nsys) ? g_systot[idx] : 0;
            loc[u] = sum;
            sum += t;
        }
        int x = sum;
#pragma unroll
        for (int o = 1; o < 32; o <<= 1) {
            int uu = __shfl_up_sync(0xffffffffu, x, o);
            if (tid >= o) x += uu;
        }
        int excl = x - sum;
        for (int u = 0; u < per && u < 8; u++) {
            int idx = bbase + u;
            if (idx < nsys && idx < NSYS_SM) s_sysoff[idx] = excl + loc[u];
        }
        if (tid == 31 && nsys < NSYS_SM) s_sysoff[nsys] = x;  // npairs
    }
    __syncthreads();
    int np = s_sysoff[nsys];

    if (blockIdx.x < WB) {
        int row = blockIdx.x * (blockDim.x >> 5) + (tid >> 5);
        if (row >= nrows) return;              // warp-uniform
        int lane = tid & 31;
        int w = tid >> 5;
        int s = row / nat, i = row - s * nat;
        int g = i >> 2, t = i & 3;
        int c0 = i >> 5;

        unsigned m = 0;
        if (lane >= c0 && lane < nch)
            m = ((const unsigned*)&g_mask[((size_t)s * ngroups + g) * nch])
                 [(lane << 2) + t];
        int cnt = __popc(m);

        int x = cnt;  // inclusive scan across lanes (chunks)
#pragma unroll
        for (int o = 1; o < 32; o <<= 1) {
            int u = __shfl_up_sync(0xffffffffu, x, o);
            if (lane >= o) x += u;
        }
        int mybase = x - cnt;
        int total = __shfl_sync(0xffffffffu, x, 31);
        if (total == 0) return;                 // warp-uniform

        {   // stage hit j-indices at their final in-row positions
            unsigned mm = m;
            int r = mybase;
            int jb = lane << 5;
            while (mm) {
                int b = __ffs(mm) - 1;
                mm &= mm - 1;
                if (r < HCAP) s_hits[w][r] = jb + b;
                r++;
            }
        }
        __syncwarp();

        const float4* pk = g_pk + (size_t)s * stride;
        float4 vi = pk[i];
        float nx = -0.5f * vi.x, ny = -0.5f * vi.y, nz = -0.5f * vi.z;  // exact
        float wi = vi.w;
        float fsrc = (float)row;
        float fsysbase = (float)(s * nat);
        int off = s_sysoff[s] + g_offsets[row];

        for (int kb = 0; kb < total; kb += 32) {
            int k = kb + lane;
            if (k < total && k < HCAP) {
                int j = s_hits[w][k];
                float4 vj = __ldg(&pk[j]);      // one LDG.128 per hit
                float tt = __fmul_rn(nx, vj.x);
                tt = __fmaf_rn(ny, vj.y, tt);
                tt = __fmaf_rn(nz, vj.z, tt);
                float d = __fadd_rn(__fadd_rn(wi, vj.w), tt);
                int pos = off + k;
                if (pos < maxp) {
                    float fdst = fsysbase + (float)j;
                    out[pos]            = fsrc;
                    out[maxp + pos]     = fdst;
                    out[2 * maxp + pos] = fdst;
                    out[3 * maxp + pos] = fsrc;
                    out[4 * maxp + pos] = d;
                    out[5 * maxp + pos] = d;
                }
            }
        }
    } else {
        int pb = blockIdx.x - WB;
        if (pb == 0 && tid == 0) out[6 * maxp] = (float)np;
        int k0 = (pb * blockDim.x + tid) * 4;
        if (k0 >= maxp) return;
        if (k0 >= np && k0 + 3 < maxp && vec_ok) {
            float4 pv = make_float4(padval, padval, padval, padval);
            float4 cv = make_float4(CUT2, CUT2, CUT2, CUT2);
            *(float4*)(out + k0)            = pv;
            *(float4*)(out + maxp + k0)     = pv;
            *(float4*)(out + 2 * maxp + k0) = pv;
            *(float4*)(out + 3 * maxp + k0) = pv;
            *(float4*)(out + 4 * maxp + k0) = cv;
            *(float4*)(out + 5 * maxp + k0) = cv;
        } else {
#pragma unroll
            for (int u = 0; u < 4; u++) {
                int k = k0 + u;
                if (k < maxp && k >= np) {
                    out[k]            = padval;
                    out[maxp + k]     = padval;
                    out[2 * maxp + k] = padval;
                    out[3 * maxp + k] = padval;
                    out[4 * maxp + k] = CUT2;
                    out[5 * maxp + k] = CUT2;
                }
            }
        }
    }
}

extern "C" void kernel_launch(void* const* d_in, const int* in_sizes, int n_in,
                              void* d_out, int out_size) {
    const float* coords = (const float*)d_in[0];
    int n    = in_sizes[1];          // total atoms
    int nsys = in_sizes[2];          // systems
    int nat  = n / nsys;
    int maxp = (out_size - 1) / 6;   // MAX_PAIRS
    float* out = (float*)d_out;

    int nch = (nat + 31) >> 5;            // 32-wide j-chunks per row (<= 32)
    int ngroups = (nat + 3) >> 2;         // 4-row mask groups per system
    int stride = nch << 5;                // padded atoms per system
    size_t smem_sweep = (size_t)stride * sizeof(float4);
    int vec_ok = ((maxp & 3) == 0) ? 1 : 0;

    int WB = (n + 7) / 8;                          // write blocks (8 warps ea)
    int PB = (maxp + 256 * 4 - 1) / (256 * 4);     // pad blocks

    prep_kernel<<<(nsys * stride + 255) / 256, 256>>>(coords, nat, stride,
                                                      nsys);
    sweep_kernel<<<dim3(nsys, 16), 256, smem_sweep>>>(nat, nch, ngroups);
    scan_sys_kernel<<<nsys, 1024>>>(nat);
    output_kernel<<<WB + PB, 256>>>(out, maxp, n, nat, nsys, nch, ngroups,
                                    stride, WB, (float)n, vec_ok);
}

// round 16
// speedup vs baseline: 1.0026x; 1.0026x over previous
#include <cuda_runtime.h>

#define CUT2 25.0f
#define QS 4            // j-quarter split: 4 warps share one row-block
#define HCAP 128        // per-warp staged-hit capacity (max row degree ~60)
#define OW 16           // output: warps (=rows) per 512-thread block
#define NROWS_CAP 65536
#define NGRP_CAP  (NROWS_CAP / 4)
#define MAXCH 32        // max 32-wide j-chunks per row (nat <= 1024)
#define NPK_CAP 131072
#define NSYS_CAP 2048

// Scratch (static __device__, allocation-free).
__device__ float4 g_pk[NPK_CAP];            // (2x,2y,2z,sq) per atom, padded
__device__ uint4  g_mask[(size_t)NGRP_CAP * MAXCH];   // R9-proven layout, 8 MB
__device__ int    g_cntp[(size_t)NROWS_CAP * QS];     // per-(row, quarter)
__device__ int    g_offsets[NROWS_CAP];     // within-system exclusive prefix
__device__ int    g_systot[NSYS_CAP];       // per-system totals

// ---- bit-exact reference arithmetic (DO NOT CHANGE) ----
__device__ __forceinline__ float sqnorm3(float x, float y, float z) {
    return __fadd_rn(__fadd_rn(__fmul_rn(x, x), __fmul_rn(y, y)), __fmul_rn(z, z));
}
// --------------------------------------------------------

// K0: pack (2x, 2y, 2z, sq) per atom; sentinel (0,0,0,1e30) pads each system
// to stride = nch*32 so sweep/output need no bounds checks.
__global__ void prep_kernel(const float* __restrict__ coords, int nat,
                            int stride, int nsys) {
    int idx = blockIdx.x * blockDim.x + threadIdx.x;
    if (idx >= nsys * stride) return;
    int s = idx / stride, j = idx - s * stride;
    float4 r = make_float4(0.f, 0.f, 0.f, 1e30f);
    if (j < nat) {
        const float* p = coords + ((size_t)s * nat + j) * 3;
        float x = p[0], y = p[1], z = p[2];
        r = make_float4(2.0f * x, 2.0f * y, 2.0f * z, sqnorm3(x, y, z));
    }
    g_pk[idx] = r;
}

extern __shared__ float4 s_at[];  // stride entries: (2x, 2y, 2z, sq)

// K1 (R13-proven body, pk-copy fill): row-per-lane mask sweep with j-quarter
// split. Work item (blk, q): lane l owns row 32*blk + l; the warp walks
// chunks c = blk+q, blk+q+QS, ... s_at[j] loads are warp-broadcast. Each lane
// accumulates its row's 32-bit mask in a register (FSETP + predicated OR).
// The negated/halved row regs make the FMA chain produce -2*dot exactly, so
// d = rn(rn(wi+wj) - 2*dot): bit-identical to the reference d12.
__global__ void sweep_kernel(int nat, int nch, int ngroups) {
    int s = blockIdx.x;
    int stride = nch << 5;
    {
        const float4* src = g_pk + (size_t)s * stride;
        for (int t = threadIdx.x; t < stride; t += blockDim.x)
            s_at[t] = src[t];              // LDG.128 -> STS.128 copy
        __syncthreads();
    }

    int lane = threadIdx.x & 31;
    int wj   = (threadIdx.x >> 5) + blockIdx.y * (blockDim.x >> 5);
    int W    = (blockDim.x >> 5) * gridDim.y;
    int NI   = nch * QS;                 // flattened items (blk, q)

    for (int base_it = 0; base_it * W < NI; base_it++) {
        int it = (base_it & 1) ? ((base_it + 1) * W - 1 - wj)
                               : (base_it * W + wj);
        if (it >= NI) continue;
        int blk = it >> 2, q = it & 3;

        int R = blk << 5;
        int i = R + lane;                  // this lane's row (may be sentinel)
        float4 v = s_at[i];
        float nx = -0.5f * v.x, ny = -0.5f * v.y, nz = -0.5f * v.z;  // exact
        float wi = v.w;

        int g4 = i >> 2;
        bool g4ok = (g4 < ngroups);
        unsigned* mp = ((unsigned*)g_mask) +
                       (((size_t)s * ngroups + g4) * nch) * 4 + (i & 3);
        int cnt = 0;
        int c = blk + q;

        // Diagonal chunk (only item q == 0): keep bits j_local > lane.
        if (q == 0 && c < nch) {
            const float4* jp = s_at + (c << 5);
            unsigned m = 0;
#pragma unroll
            for (int k = 0; k < 32; k++) {
                float4 aj = jp[k];
                float t = __fmul_rn(nx, aj.x);
                t = __fmaf_rn(ny, aj.y, t);
                t = __fmaf_rn(nz, aj.z, t);
                float w = __fadd_rn(wi, aj.w);
                float d = __fadd_rn(w, t);
                if (d < CUT2) m |= (1u << k);
            }
            m &= (0xFFFFFFFEu << lane);
            if (g4ok) mp[(size_t)c << 2] = m;
            cnt += __popc(m);
            c += QS;
        }

        for (; c < nch; c += QS) {
            const float4* jp = s_at + (c << 5);
            unsigned m = 0;
#pragma unroll
            for (int k = 0; k < 32; k++) {
                float4 aj = jp[k];
                float t = __fmul_rn(nx, aj.x);
                t = __fmaf_rn(ny, aj.y, t);
                t = __fmaf_rn(nz, aj.z, t);
                float w = __fadd_rn(wi, aj.w);
                float d = __fadd_rn(w, t);
                if (d < CUT2) m |= (1u << k);
            }
            if (g4ok) mp[(size_t)c << 2] = m;
            cnt += __popc(m);
        }

        if (i < nat) g_cntp[((size_t)s * nat + i) * QS + q] = cnt;
    }
}

// K2 (R13-proven): per-system exclusive scan; row count = sum of 4 partials.
__global__ void scan_sys_kernel(int nat) {
    __shared__ int wsum[32];
    int s = blockIdx.x;
    int tid = threadIdx.x;
    int lane = tid & 31, w = tid >> 5;

    int v = 0;
    if (tid < nat) {
        int4 p = *(const int4*)&g_cntp[((size_t)s * nat + tid) * QS];
        v = p.x + p.y + p.z + p.w;
    }

    int x = v;
#pragma unroll
    for (int o = 1; o < 32; o <<= 1) {
        int u = __shfl_up_sync(0xffffffffu, x, o);
        if (lane >= o) x += u;
    }
    if (lane == 31) wsum[w] = x;
    __syncthreads();
    if (w == 0) {
        int y = wsum[lane];
#pragma unroll
        for (int o = 1; o < 32; o <<= 1) {
            int u = __shfl_up_sync(0xffffffffu, y, o);
            if (lane >= o) y += u;
        }
        wsum[lane] = y;
    }
    __syncthreads();
    int incl = x + ((w > 0) ? wsum[w - 1] : 0);
    if (tid < nat) g_offsets[s * nat + tid] = incl - v;
    if (tid == nat - 1) g_systot[s] = incl;
}

// K3: fused output with smem-cached system atoms. 512-thread blocks; write
// blocks handle 16 rows of ONE system: the block cooperatively copies that
// system's packed atoms (g_pk) into smem, then each warp processes one row —
// mask load, popc-scan, per-warp staging of hit j's (R13-proven), and per-hit
// gather via LDS.128 (scattered shared gather ~4-8 cyc/warp vs ~32 L1
// wavefronts for global). d12 via the negated-row form: bit-identical.
// Pad blocks (blockIdx >= WB) fill the padding region concurrently.
// Output float32 layout (maxp = MAX_PAIRS):
//   [0,M): src   [M,2M): dst    (edge_src = concat(src,dst))
//   [2M,3M): dst [3M,4M): src   (edge_dst = concat(dst,src))
//   [4M,5M): d12 [5M,6M): d12   [6M]: npairs
__global__ void __launch_bounds__(512)
output_kernel(float* __restrict__ out, int maxp, int nat, int nsys, int nch,
              int ngroups, int stride, int nwb, int WB, float padval,
              int vec_ok) {
    __shared__ int s_hits[OW][HCAP];
    __shared__ int s_off2[2];   // [0] = sysoff of this block's system, [1] = np
    int tid = threadIdx.x;
    bool is_write = (blockIdx.x < WB);
    int s = is_write ? (int)(blockIdx.x / nwb) : 0;

    if (tid < 32) {   // warp 0: sysoff[s] and npairs by masked reduction
        int per = (nsys + 31) >> 5;
        int acc_s = 0, acc_all = 0;
        for (int u = 0; u < per; u++) {
            int idx = tid + (u << 5);
            int t = (idx < nsys) ? g_systot[idx] : 0;
            if (idx < s) acc_s += t;
            acc_all += t;
        }
#pragma unroll
        for (int o = 16; o; o >>= 1) {
            acc_s   += __shfl_down_sync(0xffffffffu, acc_s, o);
            acc_all += __shfl_down_sync(0xffffffffu, acc_all, o);
        }
        if (tid == 0) { s_off2[0] = acc_s; s_off2[1] = acc_all; }
    }
    if (is_write) {
        const float4* src = g_pk + (size_t)s * stride;
        for (int t = tid; t < stride; t += blockDim.x)
            s_at[t] = src[t];
    }
    __syncthreads();
    int np = s_off2[1];

    if (is_write) {
        int w = tid >> 5, lane = tid & 31;
        int i = (blockIdx.x - s * nwb) * OW + w;   // row within system
        if (i >= nat) return;
        int row = s * nat + i;
        int g = i >> 2, t = i & 3;
        int c0 = i >> 5;

        unsigned m = 0;
        if (lane >= c0 && lane < nch)
            m = ((const unsigned*)&g_mask[((size_t)s * ngroups + g) * nch])
                 [(lane << 2) + t];
        int cnt = __popc(m);

        int x = cnt;  // inclusive scan across lanes (chunks)
#pragma unroll
        for (int o = 1; o < 32; o <<= 1) {
            int u = __shfl_up_sync(0xffffffffu, x, o);
            if (lane >= o) x += u;
        }
        int mybase = x - cnt;
        int total = __shfl_sync(0xffffffffu, x, 31);
        if (total == 0) return;                 // warp-uniform

        {   // stage hit j-indices at their final in-row positions
            unsigned mm = m;
            int r = mybase;
            int jb = lane << 5;
            while (mm) {
                int b = __ffs(mm) - 1;
                mm &= mm - 1;
                if (r < HCAP) s_hits[w][r] = jb + b;
                r++;
            }
        }
        __syncwarp();

        float4 vi = s_at[i];
        float nx = -0.5f * vi.x, ny = -0.5f * vi.y, nz = -0.5f * vi.z;  // exact
        float wi = vi.w;
        float fsrc = (float)row;
        float fsysbase = (float)(s * nat);
        int off = s_off2[0] + g_offsets[row];

        for (int kb = 0; kb < total; kb += 32) {
            int k = kb + lane;
            if (k < total && k < HCAP) {
                int j = s_hits[w][k];
                float4 vj = s_at[j];            // scattered LDS.128 (cheap)
                float tt = __fmul_rn(nx, vj.x);
                tt = __fmaf_rn(ny, vj.y, tt);
                tt = __fmaf_rn(nz, vj.z, tt);
                float d = __fadd_rn(__fadd_rn(wi, vj.w), tt);
                int pos = off + k;
                if (pos < maxp) {
                    float fdst = fsysbase + (float)j;
                    out[pos]            = fsrc;
                    out[maxp + pos]     = fdst;
                    out[2 * maxp + pos] = fdst;
                    out[3 * maxp + pos] = fsrc;
                    out[4 * maxp + pos] = d;
                    out[5 * maxp + pos] = d;
                }
            }
        }
    } else {
        int pb = blockIdx.x - WB;
        if (pb == 0 && tid == 0) out[6 * maxp] = (float)np;
        int k0 = (pb * blockDim.x + tid) * 4;
        if (k0 >= maxp) return;
        if (k0 >= np && k0 + 3 < maxp && vec_ok) {
            float4 pv = make_float4(padval, padval, padval, padval);
            float4 cv = make_float4(CUT2, CUT2, CUT2, CUT2);
            *(float4*)(out + k0)            = pv;
            *(float4*)(out + maxp + k0)     = pv;
            *(float4*)(out + 2 * maxp + k0) = pv;
            *(float4*)(out + 3 * maxp + k0) = pv;
            *(float4*)(out + 4 * maxp + k0) = cv;
            *(float4*)(out + 5 * maxp + k0) = cv;
        } else {
#pragma unroll
            for (int u = 0; u < 4; u++) {
                int k = k0 + u;
                if (k < maxp && k >= np) {
                    out[k]            = padval;
                    out[maxp + k]     = padval;
                    out[2 * maxp + k] = padval;
                    out[3 * maxp + k] = padval;
                    out[4 * maxp + k] = CUT2;
                    out[5 * maxp + k] = CUT2;
                }
            }
        }
    }
}

extern "C" void kernel_launch(void* const* d_in, const int* in_sizes, int n_in,
                              void* d_out, int out_size) {
    const float* coords = (const float*)d_in[0];
    int n    = in_sizes[1];          // total atoms
    int nsys = in_sizes[2];          // systems
    int nat  = n / nsys;
    int maxp = (out_size - 1) / 6;   // MAX_PAIRS
    float* out = (float*)d_out;

    int nch = (nat + 31) >> 5;            // 32-wide j-chunks per row (<= 32)
    int ngroups = (nat + 3) >> 2;         // 4-row mask groups per system
    int stride = nch << 5;                // padded atoms per system
    size_t smem_tile = (size_t)stride * sizeof(float4);
    int vec_ok = ((maxp & 3) == 0) ? 1 : 0;

    int nwb = (nat + OW - 1) / OW;                 // write blocks per system
    int WB  = nsys * nwb;
    int PB  = (maxp + 512 * 4 - 1) / (512 * 4);    // pad blocks

    prep_kernel<<<(nsys * stride + 255) / 256, 256>>>(coords, nat, stride,
                                                      nsys);
    sweep_kernel<<<dim3(nsys, 16), 256, smem_tile>>>(nat, nch, ngroups);
    scan_sys_kernel<<<nsys, 1024>>>(nat);
    output_kernel<<<WB + PB, 512, smem_tile>>>(out, maxp, nat, nsys, nch,
                                               ngroups, stride, nwb, WB,
                                               (float)n, vec_ok);
}

// round 17
// speedup vs baseline: 1.0843x; 1.0815x over previous
#include <cuda_runtime.h>

#define CUT2 25.0f
#define QS 4            // j-quarter split: 4 warps share one row-block
#define HCAP 128        // per-warp staged-hit capacity (max row degree ~60)
#define NROWS_CAP 65536
#define NGRP_CAP  (NROWS_CAP / 4)
#define MAXCH 32        // max 32-wide j-chunks per row (nat <= 1024)
#define NPK_CAP 131072
#define NSYS_CAP 2048
#define NSYS_SM 257

// Scratch (static __device__, allocation-free).
__device__ float4 g_pk[NPK_CAP];            // (2x,2y,2z,sq) per atom, padded
__device__ uint4  g_mask[(size_t)NGRP_CAP * MAXCH];   // R9-proven layout, 8 MB
__device__ int    g_cntp[(size_t)NROWS_CAP * QS];     // per-(row, quarter)
__device__ int    g_offsets[NROWS_CAP];     // within-system exclusive prefix
__device__ int    g_systot[NSYS_CAP];       // per-system totals

// ---- bit-exact reference arithmetic (DO NOT CHANGE) ----
__device__ __forceinline__ float sqnorm3(float x, float y, float z) {
    return __fadd_rn(__fadd_rn(__fmul_rn(x, x), __fmul_rn(y, y)), __fmul_rn(z, z));
}
// gram dot via GEMM-style FMA chain: c = rn(x*x'); c = fma(y,y',c); c = fma(z,z',c)
__device__ __forceinline__ float dot3(float4 a, float4 b) {
    return __fmaf_rn(a.z, b.z, __fmaf_rn(a.y, b.y, __fmul_rn(a.x, b.x)));
}
__device__ __forceinline__ float d12_of(float4 ai, float4 aj) {
    return __fsub_rn(__fadd_rn(ai.w, aj.w), __fmul_rn(2.0f, dot3(ai, aj)));
}
// --------------------------------------------------------

// K0: pack (2x, 2y, 2z, sq) per atom; sentinel (0,0,0,1e30) pads each system
// to stride = nch*32 so the sweep needs no bounds checks.
__global__ void prep_kernel(const float* __restrict__ coords, int nat,
                            int stride, int nsys) {
    int idx = blockIdx.x * blockDim.x + threadIdx.x;
    if (idx >= nsys * stride) return;
    int s = idx / stride, j = idx - s * stride;
    float4 r = make_float4(0.f, 0.f, 0.f, 1e30f);
    if (j < nat) {
        const float* p = coords + ((size_t)s * nat + j) * 3;
        float x = p[0], y = p[1], z = p[2];
        r = make_float4(2.0f * x, 2.0f * y, 2.0f * z, sqnorm3(x, y, z));
    }
    g_pk[idx] = r;
}

extern __shared__ float4 s_at[];  // stride entries: (2x, 2y, 2z, sq)

// K1 (R13-proven body; pk-copy fill): row-per-lane mask sweep with j-quarter
// split. Work item (blk, q): lane l owns row 32*blk + l; the warp walks
// chunks c = blk+q, blk+q+QS, ... s_at[j] loads are warp-broadcast. Each lane
// accumulates its row's 32-bit mask in a register (FSETP + predicated OR).
// The negated/halved row regs make the FMA chain produce -2*dot exactly, so
// d = rn(rn(wi+wj) - 2*dot): bit-identical to the reference d12.
__global__ void sweep_kernel(int nat, int nch, int ngroups) {
    int s = blockIdx.x;
    int stride = nch << 5;
    {
        const float4* src = g_pk + (size_t)s * stride;
        for (int t = threadIdx.x; t < stride; t += blockDim.x)
            s_at[t] = src[t];              // LDG.128 -> STS.128 copy
        __syncthreads();
    }

    int lane = threadIdx.x & 31;
    int wj   = (threadIdx.x >> 5) + blockIdx.y * (blockDim.x >> 5);
    int W    = (blockDim.x >> 5) * gridDim.y;
    int NI   = nch * QS;                 // flattened items (blk, q)

    // Zigzag item assignment for balance.
    for (int base_it = 0; base_it * W < NI; base_it++) {
        int it = (base_it & 1) ? ((base_it + 1) * W - 1 - wj)
                               : (base_it * W + wj);
        if (it >= NI) continue;
        int blk = it >> 2, q = it & 3;

        int R = blk << 5;
        int i = R + lane;                  // this lane's row (may be sentinel)
        float4 v = s_at[i];
        float nx = -0.5f * v.x, ny = -0.5f * v.y, nz = -0.5f * v.z;  // exact
        float wi = v.w;

        int g4 = i >> 2;
        bool g4ok = (g4 < ngroups);
        unsigned* mp = ((unsigned*)g_mask) +
                       (((size_t)s * ngroups + g4) * nch) * 4 + (i & 3);
        int cnt = 0;
        int c = blk + q;

        // Diagonal chunk (only item q == 0): keep bits j_local > lane.
        if (q == 0 && c < nch) {
            const float4* jp = s_at + (c << 5);
            unsigned m = 0;
#pragma unroll
            for (int k = 0; k < 32; k++) {
                float4 aj = jp[k];
                float t = __fmul_rn(nx, aj.x);
                t = __fmaf_rn(ny, aj.y, t);
                t = __fmaf_rn(nz, aj.z, t);
                float w = __fadd_rn(wi, aj.w);
                float d = __fadd_rn(w, t);
                if (d < CUT2) m |= (1u << k);
            }
            m &= (0xFFFFFFFEu << lane);
            if (g4ok) mp[(size_t)c << 2] = m;
            cnt += __popc(m);
            c += QS;
        }

        // Clean chunks: all bits valid; sentinels kill j >= nat.
        for (; c < nch; c += QS) {
            const float4* jp = s_at + (c << 5);
            unsigned m = 0;
#pragma unroll
            for (int k = 0; k < 32; k++) {
                float4 aj = jp[k];
                float t = __fmul_rn(nx, aj.x);
                t = __fmaf_rn(ny, aj.y, t);
                t = __fmaf_rn(nz, aj.z, t);
                float w = __fadd_rn(wi, aj.w);
                float d = __fadd_rn(w, t);
                if (d < CUT2) m |= (1u << k);
            }
            if (g4ok) mp[(size_t)c << 2] = m;
            cnt += __popc(m);
        }

        if (i < nat) g_cntp[((size_t)s * nat + i) * QS + q] = cnt;
    }
}

// K2 (R13-proven): per-system exclusive scan; row count = sum of 4 partials.
__global__ void scan_sys_kernel(int nat) {
    __shared__ int wsum[32];
    int s = blockIdx.x;
    int tid = threadIdx.x;
    int lane = tid & 31, w = tid >> 5;

    int v = 0;
    if (tid < nat) {
        int4 p = *(const int4*)&g_cntp[((size_t)s * nat + tid) * QS];
        v = p.x + p.y + p.z + p.w;
    }

    int x = v;
#pragma unroll
    for (int o = 1; o < 32; o <<= 1) {
        int u = __shfl_up_sync(0xffffffffu, x, o);
        if (lane >= o) x += u;
    }
    if (lane == 31) wsum[w] = x;
    __syncthreads();
    if (w == 0) {
        int y = wsum[lane];
#pragma unroll
        for (int o = 1; o < 32; o <<= 1) {
            int u = __shfl_up_sync(0xffffffffu, y, o);
            if (lane >= o) y += u;
        }
        wsum[lane] = y;
    }
    __syncthreads();
    int incl = x + ((w > 0) ? wsum[w - 1] : 0);
    if (tid < nat) g_offsets[s * nat + tid] = incl - v;
    if (tid == nat - 1) g_systot[s] = incl;
}

// K3 (R13-proven, verbatim): fused output, hit-parallel via per-warp smem
// staging. One warp per row; lane c loads chunk c's mask; shfl-scan of
// popcounts gives per-chunk bases; each lane serially STS's its own chunk's
// hit j-indices at their final positions; after __syncwarp, lane k handles
// the k-th hit (3 coord LDGs, L2-resident), recomputing d12 bit-exactly.
// Stores coalesced. Pad blocks run concurrently.
// Output float32 layout (maxp = MAX_PAIRS):
//   [0,M): src   [M,2M): dst    (edge_src = concat(src,dst))
//   [2M,3M): dst [3M,4M): src   (edge_dst = concat(dst,src))
//   [4M,5M): d12 [5M,6M): d12   [6M]: npairs
__global__ void output_kernel(const float* __restrict__ coords,
                              float* __restrict__ out, int maxp, int nrows,
                              int nat, int nsys, int nch, int ngroups,
                              int WB, float padval, int vec_ok) {
    __shared__ int s_sysoff[NSYS_SM];
    __shared__ int s_hits[8][HCAP];
    int tid = threadIdx.x;
    if (tid < 32) {
        int per = (nsys + 31) >> 5;
        int bbase = tid * per;
        int loc[8];
        int sum = 0;
        for (int u = 0; u < per && u < 8; u++) {
            int idx = bbase + u;
            int t = (idx < nsys) ? g_systot[idx] : 0;
            loc[u] = sum;
            sum += t;
        }
        int x = sum;
#pragma unroll
        for (int o = 1; o < 32; o <<= 1) {
            int uu = __shfl_up_sync(0xffffffffu, x, o);
            if (tid >= o) x += uu;
        }
        int excl = x - sum;
        for (int u = 0; u < per && u < 8; u++) {
            int idx = bbase + u;
            if (idx < nsys && idx < NSYS_SM) s_sysoff[idx] = excl + loc[u];
        }
        if (tid == 31 && nsys < NSYS_SM) s_sysoff[nsys] = x;  // npairs
    }
    __syncthreads();
    int np = s_sysoff[nsys];

    if (blockIdx.x < WB) {
        int row = blockIdx.x * (blockDim.x >> 5) + (tid >> 5);
        if (row >= nrows) return;              // warp-uniform
        int lane = tid & 31;
        int w = tid >> 5;
        int s = row / nat, i = row - s * nat;
        int g = i >> 2, t = i & 3;
        int c0 = i >> 5;

        unsigned m = 0;
        if (lane >= c0 && lane < nch)
            m = ((const unsigned*)&g_mask[((size_t)s * ngroups + g) * nch])
                 [(lane << 2) + t];
        int cnt = __popc(m);

        int x = cnt;  // inclusive scan across lanes (chunks)
#pragma unroll
        for (int o = 1; o < 32; o <<= 1) {
            int u = __shfl_up_sync(0xffffffffu, x, o);
            if (lane >= o) x += u;
        }
        int mybase = x - cnt;
        int total = __shfl_sync(0xffffffffu, x, 31);
        if (total == 0) return;                 // warp-uniform
        int tclamp = (total < HCAP) ? total : HCAP;

        {   // stage hit j-indices at their final in-row positions
            unsigned mm = m;
            int r = mybase;
            int jb = lane << 5;
            while (mm) {
                int b = __ffs(mm) - 1;
                mm &= mm - 1;
                if (r < HCAP) s_hits[w][r] = jb + b;
                r++;
            }
        }
        __syncwarp();

        const float* ci = coords + (size_t)row * 3;
        float xi = __ldg(ci), yi = __ldg(ci + 1), zi = __ldg(ci + 2);
        float4 ai = make_float4(xi, yi, zi, sqnorm3(xi, yi, zi));
        float fsrc = (float)row;
        float fsysbase = (float)(s * nat);
        int off = s_sysoff[s] + g_offsets[row];
        int sysbase = s * nat;

        for (int kb = 0; kb < tclamp; kb += 32) {
            int k = kb + lane;
            if (k < tclamp) {
                int j = s_hits[w][k];
                const float* cj = coords + (size_t)(sysbase + j) * 3;
                float xj = __ldg(cj), yj = __ldg(cj + 1), zj = __ldg(cj + 2);
                float4 aj = make_float4(xj, yj, zj, sqnorm3(xj, yj, zj));
                float d = d12_of(ai, aj);
                int pos = off + k;
                if (pos < maxp) {
                    float fdst = fsysbase + (float)j;
                    out[pos]            = fsrc;
                    out[maxp + pos]     = fdst;
                    out[2 * maxp + pos] = fdst;
                    out[3 * maxp + pos] = fsrc;
                    out[4 * maxp + pos] = d;
                    out[5 * maxp + pos] = d;
                }
            }
        }
    } else {
        int pb = blockIdx.x - WB;
        if (pb == 0 && tid == 0) out[6 * maxp] = (float)np;
        int k0 = (pb * blockDim.x + tid) * 4;
        if (k0 >= maxp) return;
        if (k0 >= np && k0 + 3 < maxp && vec_ok) {
            float4 pv = make_float4(padval, padval, padval, padval);
            float4 cv = make_float4(CUT2, CUT2, CUT2, CUT2);
            *(float4*)(out + k0)            = pv;
            *(float4*)(out + maxp + k0)     = pv;
            *(float4*)(out + 2 * maxp + k0) = pv;
            *(float4*)(out + 3 * maxp + k0) = pv;
            *(float4*)(out + 4 * maxp + k0) = cv;
            *(float4*)(out + 5 * maxp + k0) = cv;
        } else {
#pragma unroll
            for (int u = 0; u < 4; u++) {
                int k = k0 + u;
                if (k < maxp && k >= np) {
                    out[k]            = padval;
                    out[maxp + k]     = padval;
                    out[2 * maxp + k] = padval;
                    out[3 * maxp + k] = padval;
                    out[4 * maxp + k] = CUT2;
                    out[5 * maxp + k] = CUT2;
                }
            }
        }
    }
}

extern "C" void kernel_launch(void* const* d_in, const int* in_sizes, int n_in,
                              void* d_out, int out_size) {
    const float* coords = (const float*)d_in[0];
    int n    = in_sizes[1];          // total atoms
    int nsys = in_sizes[2];          // systems
    int nat  = n / nsys;
    int maxp = (out_size - 1) / 6;   // MAX_PAIRS
    float* out = (float*)d_out;

    int nch = (nat + 31) >> 5;            // 32-wide j-chunks per row (<= 32)
    int ngroups = (nat + 3) >> 2;         // 4-row mask groups per system
    int stride = nch << 5;                // padded atoms per system
    size_t smem_sweep = (size_t)stride * sizeof(float4);
    int vec_ok = ((maxp & 3) == 0) ? 1 : 0;

    int WB = (n + 7) / 8;                          // write blocks (8 warps ea)
    int PB = (maxp + 256 * 4 - 1) / (256 * 4);     // pad blocks

    prep_kernel<<<(nsys * stride + 255) / 256, 256>>>(coords, nat, stride,
                                                      nsys);
    sweep_kernel<<<dim3(nsys, 16), 256, smem_sweep>>>(nat, nch, ngroups);
    scan_sys_kernel<<<nsys, 1024>>>(nat);
    output_kernel<<<WB + PB, 256>>>(coords, out, maxp, n, nat, nsys, nch,
                                    ngroups, WB, (float)n, vec_ok);
}